// round 1
// baseline (speedup 1.0000x reference)
#include <cuda_runtime.h>
#include <cuda_bf16.h>

// ---------------------------------------------------------------------------
// Cross_26998164423018: dual-LN -> QKV proj -> sigmoid attention -> out proj
//  + residual -> final LN.   B=8, N=2048, C=576, H=1, D=576.
// Round 1: fp32 SIMT baseline. 128x128x8 SMEM-tiled GEMM, 8x8 microtile.
// ---------------------------------------------------------------------------

#define CDIM   576
#define NTOK   2048
#define BATCH  8
#define ROWS   (BATCH * NTOK)          // 16384
#define ATT_SCALE 0.0416666679f        // 576^-0.5 = 1/24

// Scratch (static device memory; allocation APIs are forbidden)
__device__ float g_xn[(size_t)ROWS * CDIM];
__device__ float g_yn[(size_t)ROWS * CDIM];
__device__ float g_q [(size_t)ROWS * CDIM];
__device__ float g_k [(size_t)ROWS * CDIM];
__device__ float g_v [(size_t)ROWS * CDIM];
__device__ float g_o [(size_t)ROWS * CDIM];
__device__ float g_p [(size_t)ROWS * CDIM];
__device__ float g_attn[(size_t)BATCH * NTOK * NTOK];   // 134 MB

// ---------------------------------------------------------------------------
// LayerNorm: one block per row of 576. blockDim = 256.
// ---------------------------------------------------------------------------
__global__ __launch_bounds__(256) void ln_kernel(
    const float* __restrict__ x, const float* __restrict__ g,
    const float* __restrict__ b, float* __restrict__ out)
{
    const long row = blockIdx.x;
    const float* xr = x + row * (long)CDIM;
    float* orow = out + row * (long)CDIM;
    const int t = threadIdx.x;

    float v0 = xr[t];
    float v1 = xr[t + 256];
    float v2 = 0.f;
    if (t < 64) v2 = xr[t + 512];

    float s  = v0 + v1 + v2;
    float ss = v0 * v0 + v1 * v1 + v2 * v2;

    #pragma unroll
    for (int o = 16; o > 0; o >>= 1) {
        s  += __shfl_xor_sync(0xFFFFFFFFu, s,  o);
        ss += __shfl_xor_sync(0xFFFFFFFFu, ss, o);
    }

    __shared__ float sh_s[8], sh_ss[8];
    const int w = t >> 5, l = t & 31;
    if (l == 0) { sh_s[w] = s; sh_ss[w] = ss; }
    __syncthreads();

    float stot = 0.f, sstot = 0.f;
    #pragma unroll
    for (int i = 0; i < 8; i++) { stot += sh_s[i]; sstot += sh_ss[i]; }

    const float inv_n = 1.0f / (float)CDIM;
    const float mean = stot * inv_n;
    const float var  = sstot * inv_n - mean * mean;
    const float rstd = rsqrtf(var + 1e-5f);

    orow[t]       = (v0 - mean) * rstd * g[t]       + b[t];
    orow[t + 256] = (v1 - mean) * rstd * g[t + 256] + b[t + 256];
    if (t < 64)
        orow[t + 512] = (v2 - mean) * rstd * g[t + 512] + b[t + 512];
}

// ---------------------------------------------------------------------------
// Tiled GEMM: C[M,N] = A[M,K] @ op(B)
//   BT=true : op(B) = B^T where B is [N,K] row-major  (both operands K-inner)
//   BT=false: op(B) = B   where B is [K,N] row-major
// EPI: 0 = plain store, 1 = sigmoid(x * ATT_SCALE), 2 = + bias[n] + resid[m,n]
// blockDim = 256, tile 128x128, K-step 8, 8x8 microtile (4+4 split at +64).
// ---------------------------------------------------------------------------
template<bool BT, int EPI>
__global__ __launch_bounds__(256) void gemm_tile(
    const float* __restrict__ Ag, const float* __restrict__ Bg,
    float* __restrict__ Cg,
    int M, int N, int K, long sA, long sB, long sC,
    const float* __restrict__ bias, const float* __restrict__ resid)
{
    const float* A = Ag + (long)blockIdx.z * sA;
    const float* B = Bg + (long)blockIdx.z * sB;
    float*       C = Cg + (long)blockIdx.z * sC;

    const int m0 = blockIdx.y * 128;
    const int n0 = blockIdx.x * 128;

    __shared__ float As[8][128];
    __shared__ float Bs[8][128];

    const int tid = threadIdx.x;
    const int tx = tid & 15;       // 0..15 -> n microtile
    const int ty = tid >> 4;       // 0..15 -> m microtile

    const int lrow = tid >> 1;         // 0..127 (A / BT-B tile row)
    const int lkp  = (tid & 1) * 4;    // 0 or 4 (k sub-chunk)

    float acc[8][8];
    #pragma unroll
    for (int i = 0; i < 8; i++)
        #pragma unroll
        for (int j = 0; j < 8; j++) acc[i][j] = 0.f;

    for (int k0 = 0; k0 < K; k0 += 8) {
        // ---- load A tile [128 x 8] ----
        {
            float4 av = make_float4(0.f, 0.f, 0.f, 0.f);
            const int gm = m0 + lrow;
            if (gm < M)
                av = *reinterpret_cast<const float4*>(A + (long)gm * K + k0 + lkp);
            As[lkp + 0][lrow] = av.x; As[lkp + 1][lrow] = av.y;
            As[lkp + 2][lrow] = av.z; As[lkp + 3][lrow] = av.w;
        }
        // ---- load B tile ----
        if (BT) {
            float4 bv = make_float4(0.f, 0.f, 0.f, 0.f);
            const int gn = n0 + lrow;
            if (gn < N)
                bv = *reinterpret_cast<const float4*>(B + (long)gn * K + k0 + lkp);
            Bs[lkp + 0][lrow] = bv.x; Bs[lkp + 1][lrow] = bv.y;
            Bs[lkp + 2][lrow] = bv.z; Bs[lkp + 3][lrow] = bv.w;
        } else {
            const int bk = tid >> 5;          // 0..7
            const int bn = (tid & 31) * 4;    // 0..124
            float4 bv = make_float4(0.f, 0.f, 0.f, 0.f);
            const int gn = n0 + bn;
            if (gn < N)   // N % 4 == 0 for all our shapes
                bv = *reinterpret_cast<const float4*>(B + (long)(k0 + bk) * N + gn);
            *reinterpret_cast<float4*>(&Bs[bk][bn]) = bv;
        }
        __syncthreads();

        #pragma unroll
        for (int kk = 0; kk < 8; kk++) {
            float ar[8], br[8];
            *reinterpret_cast<float4*>(ar)     = *reinterpret_cast<const float4*>(&As[kk][ty * 4]);
            *reinterpret_cast<float4*>(ar + 4) = *reinterpret_cast<const float4*>(&As[kk][64 + ty * 4]);
            *reinterpret_cast<float4*>(br)     = *reinterpret_cast<const float4*>(&Bs[kk][tx * 4]);
            *reinterpret_cast<float4*>(br + 4) = *reinterpret_cast<const float4*>(&Bs[kk][64 + tx * 4]);
            #pragma unroll
            for (int i = 0; i < 8; i++)
                #pragma unroll
                for (int j = 0; j < 8; j++)
                    acc[i][j] += ar[i] * br[j];
        }
        __syncthreads();
    }

    // ---- epilogue ----
    #pragma unroll
    for (int i = 0; i < 8; i++) {
        const int m = m0 + ((i < 4) ? (ty * 4 + i) : (64 + ty * 4 + i - 4));
        if (m >= M) continue;
        #pragma unroll
        for (int j = 0; j < 8; j++) {
            const int n = n0 + ((j < 4) ? (tx * 4 + j) : (64 + tx * 4 + j - 4));
            if (n >= N) continue;
            float v = acc[i][j];
            if (EPI == 1) v = 1.0f / (1.0f + __expf(-v * ATT_SCALE));
            if (EPI == 2) v += bias[n] + resid[(long)m * N + n];
            C[(long)m * N + n] = v;
        }
    }
}

// ---------------------------------------------------------------------------
// Launch sequence
// ---------------------------------------------------------------------------
extern "C" void kernel_launch(void* const* d_in, const int* in_sizes, int n_in,
                              void* d_out, int out_size)
{
    const float* x  = (const float*)d_in[0];
    const float* y  = (const float*)d_in[1];
    const float* Wq = (const float*)d_in[2];
    const float* Wk = (const float*)d_in[3];
    const float* Wv = (const float*)d_in[4];
    const float* Wp = (const float*)d_in[5];
    const float* bp = (const float*)d_in[6];
    const float* gx = (const float*)d_in[7];
    const float* bx = (const float*)d_in[8];
    const float* gy = (const float*)d_in[9];
    const float* by = (const float*)d_in[10];
    const float* gz = (const float*)d_in[11];
    const float* bz = (const float*)d_in[12];
    float* out = (float*)d_out;

    float *xn, *yn, *q, *k, *v, *o, *p, *attn;
    cudaGetSymbolAddress((void**)&xn,   g_xn);
    cudaGetSymbolAddress((void**)&yn,   g_yn);
    cudaGetSymbolAddress((void**)&q,    g_q);
    cudaGetSymbolAddress((void**)&k,    g_k);
    cudaGetSymbolAddress((void**)&v,    g_v);
    cudaGetSymbolAddress((void**)&o,    g_o);
    cudaGetSymbolAddress((void**)&p,    g_p);
    cudaGetSymbolAddress((void**)&attn, g_attn);

    // 1. LayerNorms
    ln_kernel<<<ROWS, 256>>>(x, gx, bx, xn);
    ln_kernel<<<ROWS, 256>>>(y, gy, by, yn);

    // 2. Projections: q = yn @ Wq^T, k = xn @ Wk^T, v = xn @ Wv^T
    //    M=16384, N=576, K=576. grid: x = ceil(576/128)=5, y = 16384/128 = 128
    {
        dim3 grid(5, 128, 1);
        gemm_tile<true, 0><<<grid, 256>>>(yn, Wq, q, ROWS, CDIM, CDIM, 0, 0, 0, nullptr, nullptr);
        gemm_tile<true, 0><<<grid, 256>>>(xn, Wk, k, ROWS, CDIM, CDIM, 0, 0, 0, nullptr, nullptr);
        gemm_tile<true, 0><<<grid, 256>>>(xn, Wv, v, ROWS, CDIM, CDIM, 0, 0, 0, nullptr, nullptr);
    }

    // 3. attn = sigmoid(Q @ K^T * scale), per batch: [2048 x 2048], K=576
    {
        dim3 grid(16, 16, BATCH);
        gemm_tile<true, 1><<<grid, 256>>>(
            q, k, attn, NTOK, NTOK, CDIM,
            (long)NTOK * CDIM, (long)NTOK * CDIM, (long)NTOK * NTOK,
            nullptr, nullptr);
    }

    // 4. O = attn @ V, per batch: M=2048, N=576, K=2048 (NN)
    {
        dim3 grid(5, 16, BATCH);
        gemm_tile<false, 0><<<grid, 256>>>(
            attn, v, o, NTOK, CDIM, NTOK,
            (long)NTOK * NTOK, (long)NTOK * CDIM, (long)NTOK * CDIM,
            nullptr, nullptr);
    }

    // 5. P = O @ Wp^T + bp + xn  (residual w/ normalized x)
    {
        dim3 grid(5, 128, 1);
        gemm_tile<true, 2><<<grid, 256>>>(o, Wp, p, ROWS, CDIM, CDIM, 0, 0, 0, bp, xn);
    }

    // 6. out = LN(P)
    ln_kernel<<<ROWS, 256>>>(p, gz, bz, out);
}

// round 3
// speedup vs baseline: 2.7035x; 2.7035x over previous
#include <cuda_runtime.h>
#include <cuda_bf16.h>
#include <cstdint>

// ===========================================================================
// Cross_26998164423018  (B=8, N=2048, C=576, H=1)
// Round 3: mma.sync m16n8k8 tf32 GEMM (portable tensor-core path; tcgen05 is
// not reachable from this build's .target sm_103), 3-stage cp.async pipeline.
// ===========================================================================

#define CDIM   576
#define NTOK   2048
#define BATCH  8
#define ROWS   (BATCH * NTOK)          // 16384
#define ATT_SCALE 0.0416666679f        // 1/24

#define STAGES     3
#define SA_STRIDE  20                  // floats per smem row (80B, conflict-free)
#define STAGE_BYTES (2 * 128 * SA_STRIDE * 4)   // A + B tiles = 20480
#define ESTRIDE    132                 // epilogue smem stride (float4-aligned)
#define SMEM_SZ    (128 * ESTRIDE * 4) // 67584 > 3*20480

// ------------------------- scratch (static device mem) ---------------------
__device__ float g_xnf[(size_t)ROWS * CDIM];
__device__ float g_xnr[(size_t)ROWS * CDIM];
__device__ float g_ynr[(size_t)ROWS * CDIM];
__device__ float g_wq [(size_t)CDIM * CDIM];
__device__ float g_wk [(size_t)CDIM * CDIM];
__device__ float g_wv [(size_t)CDIM * CDIM];
__device__ float g_wp [(size_t)CDIM * CDIM];
__device__ float g_q  [(size_t)ROWS * CDIM];
__device__ float g_k  [(size_t)ROWS * CDIM];
__device__ float g_vt [(size_t)BATCH * CDIM * NTOK];   // [b][n][t]
__device__ float g_o  [(size_t)ROWS * CDIM];
__device__ float g_attn[(size_t)BATCH * NTOK * NTOK];  // 134 MB
__device__ float g_p  [(size_t)ROWS * CDIM];

// ------------------------------- helpers -----------------------------------
__device__ __forceinline__ uint32_t smem_u32(const void* p) {
    uint32_t a;
    asm("{ .reg .u64 t; cvta.to.shared.u64 t, %1; cvt.u32.u64 %0, t; }"
        : "=r"(a) : "l"(p));
    return a;
}
__device__ __forceinline__ float tf32r(float x) {
    float r; asm("cvt.rna.tf32.f32 %0, %1;" : "=f"(r) : "f"(x)); return r;
}
__device__ __forceinline__ void cpa16(uint32_t dst, const float* src, uint32_t sz) {
    asm volatile("cp.async.cg.shared.global [%0], [%1], 16, %2;"
                 :: "r"(dst), "l"(src), "r"(sz) : "memory");
}
__device__ __forceinline__ void cpa_commit() {
    asm volatile("cp.async.commit_group;" ::: "memory");
}
template<int Np> __device__ __forceinline__ void cpa_wait() {
    asm volatile("cp.async.wait_group %0;" :: "n"(Np) : "memory");
}
__device__ __forceinline__ void mma_tf32(float* c, const uint32_t* a, const uint32_t* b) {
    asm volatile(
        "mma.sync.aligned.m16n8k8.row.col.f32.tf32.tf32.f32 "
        "{%0,%1,%2,%3}, {%4,%5,%6,%7}, {%8,%9}, {%0,%1,%2,%3};"
        : "+f"(c[0]), "+f"(c[1]), "+f"(c[2]), "+f"(c[3])
        : "r"(a[0]), "r"(a[1]), "r"(a[2]), "r"(a[3]), "r"(b[0]), "r"(b[1]));
}

// ===========================================================================
// tf32 mma.sync GEMM: C[M,N] = A[M,K] @ B[N,K]^T  (both K-major, TN)
// grid: (x = N-tiles, y = M-tiles, z = batch), block = 256 (8 warps, 2x4)
// EPI: 1 = tf32-rounded store, 2 = sigmoid(x/24) rounded store,
//      3 = + bias[n] + resid[m,n] fp32 store, 4 = transposed rounded store
// ===========================================================================
template<int EPI>
__global__ __launch_bounds__(256) void mma_gemm(
    const float* __restrict__ A, const float* __restrict__ B,
    float* __restrict__ C, int M, int N, int K,
    long sAz, long sBz, long sCz, int ldC,
    const float* __restrict__ bias, const float* __restrict__ resid)
{
    extern __shared__ char smem[];
    const uint32_t sb = smem_u32(smem);
    const int tid  = threadIdx.x;
    const int lane = tid & 31;
    const int wid  = tid >> 5;
    const int m0 = blockIdx.y * 128;
    const int n0 = blockIdx.x * 128;
    const int z  = blockIdx.z;
    const int KT = K >> 4;

    // ---- gmem load pointers: thread owns row tid>>1, k-half (tid&1)*8 ----
    const int lrow = tid >> 1;
    const int lkof = (tid & 1) * 8;
    const float* aPtr = A + (size_t)z * sAz + (size_t)(m0 + lrow) * K + lkof;
    const int gn = n0 + lrow;
    const uint32_t bsz = (gn < N) ? 16u : 0u;
    const float* bPtr = B + (size_t)z * sBz + (size_t)(gn < N ? gn : 0) * K + lkof;
    const uint32_t dA = sb + (uint32_t)lrow * (SA_STRIDE * 4) + (uint32_t)(tid & 1) * 32;
    const uint32_t dB = dA + 128 * SA_STRIDE * 4;

    auto load_stage = [&](int s, int kt) {
        const uint32_t so = (uint32_t)s * STAGE_BYTES;
        const int k0 = kt * 16;
        cpa16(dA + so,      aPtr + k0,     16u);
        cpa16(dA + so + 16, aPtr + k0 + 4, 16u);
        cpa16(dB + so,      bPtr + k0,     bsz);
        cpa16(dB + so + 16, bPtr + k0 + 4, bsz);
    };

    // ---- accumulators ----
    float acc[4][4][4];
    #pragma unroll
    for (int mt = 0; mt < 4; mt++)
        #pragma unroll
        for (int nt = 0; nt < 4; nt++)
            #pragma unroll
            for (int i = 0; i < 4; i++) acc[mt][nt][i] = 0.f;

    const int warp_m = wid & 1;
    const int warp_n = wid >> 1;
    const int arow = warp_m * 64 + (lane >> 2);
    const int brow = warp_n * 32 + (lane >> 2);
    const int kcol = lane & 3;

    // ---- pipeline prologue ----
    load_stage(0, 0); cpa_commit();
    load_stage(1, 1); cpa_commit();

    for (int kt = 0; kt < KT; kt++) {
        cpa_wait<1>();
        __syncthreads();
        if (kt + 2 < KT) load_stage((kt + 2) % STAGES, kt + 2);
        cpa_commit();

        const uint32_t* uAs = (const uint32_t*)(smem + (kt % STAGES) * STAGE_BYTES);
        const uint32_t* uBs = uAs + 128 * SA_STRIDE;

        #pragma unroll
        for (int kk = 0; kk < 2; kk++) {
            const int kc = kk * 8 + kcol;
            uint32_t af[4][4];
            #pragma unroll
            for (int mt = 0; mt < 4; mt++) {
                const int r = arow + mt * 16;
                af[mt][0] = uAs[r * SA_STRIDE + kc];
                af[mt][1] = uAs[(r + 8) * SA_STRIDE + kc];
                af[mt][2] = uAs[r * SA_STRIDE + kc + 4];
                af[mt][3] = uAs[(r + 8) * SA_STRIDE + kc + 4];
            }
            uint32_t bf[4][2];
            #pragma unroll
            for (int nt = 0; nt < 4; nt++) {
                const int n = brow + nt * 8;
                bf[nt][0] = uBs[n * SA_STRIDE + kc];
                bf[nt][1] = uBs[n * SA_STRIDE + kc + 4];
            }
            #pragma unroll
            for (int mt = 0; mt < 4; mt++)
                #pragma unroll
                for (int nt = 0; nt < 4; nt++)
                    mma_tf32(acc[mt][nt], af[mt], bf[nt]);
        }
        __syncthreads();   // safe to let next iter's prefetch overwrite
    }

    // -------------------------------- epilogue --------------------------------
    __syncthreads();
    float* eb = (float*)smem;   // [128][ESTRIDE]

    #pragma unroll
    for (int mt = 0; mt < 4; mt++) {
        #pragma unroll
        for (int i = 0; i < 4; i++) {
            const int r = warp_m * 64 + mt * 16 + (lane >> 2) + ((i >= 2) ? 8 : 0);
            #pragma unroll
            for (int nt = 0; nt < 4; nt++) {
                const int c = warp_n * 32 + nt * 8 + (lane & 3) * 2 + (i & 1);
                float v = acc[mt][nt][i];
                if (EPI == 1 || EPI == 4) v = tf32r(v);
                if (EPI == 2) v = tf32r(1.0f / (1.0f + __expf(-v * ATT_SCALE)));
                eb[r * ESTRIDE + c] = v;
            }
        }
    }
    __syncthreads();

    if (EPI == 4) {
        // Vt[b][n][t] = eb[t_local][n_local]; whole tile is one batch b.
        const int b = m0 >> 11;
        const int t0 = m0 & 2047;
        float* vb = C + (size_t)b * CDIM * NTOK;
        #pragma unroll
        for (int it = 0; it < 64; it++) {
            const int lin = it * 256 + tid;
            const int t = lin & 127, n = lin >> 7;
            if (n0 + n < N)
                vb[(size_t)(n0 + n) * NTOK + t0 + t] = eb[t * ESTRIDE + n];
        }
    } else {
        #pragma unroll
        for (int it = 0; it < 16; it++) {
            const int lin = it * 256 + tid;
            const int c4 = lin & 31, r = lin >> 5;
            const int n = n0 + c4 * 4;
            if (n < N) {
                float4 v4 = *(const float4*)(eb + r * ESTRIDE + c4 * 4);
                if (EPI == 3) {
                    const float4 bb = *(const float4*)(bias + n);
                    const float4 rr = *(const float4*)(resid + (size_t)(m0 + r) * ldC + n);
                    v4.x += bb.x + rr.x; v4.y += bb.y + rr.y;
                    v4.z += bb.z + rr.z; v4.w += bb.w + rr.w;
                }
                *(float4*)(C + (size_t)z * sCz + (size_t)(m0 + r) * ldC + n) = v4;
            }
        }
    }
}

// ===========================================================================
// LayerNorm over 576; writes full and/or tf32-rounded output.
// ===========================================================================
__global__ __launch_bounds__(256) void ln_kernel(
    const float* __restrict__ x, const float* __restrict__ g,
    const float* __restrict__ b, float* __restrict__ out_f,
    float* __restrict__ out_r)
{
    const long row = blockIdx.x;
    const float* xr = x + row * (long)CDIM;
    const int t = threadIdx.x;

    float v0 = xr[t];
    float v1 = xr[t + 256];
    float v2 = (t < 64) ? xr[t + 512] : 0.f;

    float s  = v0 + v1 + v2;
    float ss = v0 * v0 + v1 * v1 + v2 * v2;
    #pragma unroll
    for (int o = 16; o > 0; o >>= 1) {
        s  += __shfl_xor_sync(0xFFFFFFFFu, s,  o);
        ss += __shfl_xor_sync(0xFFFFFFFFu, ss, o);
    }
    __shared__ float sh_s[8], sh_ss[8];
    const int w = t >> 5, l = t & 31;
    if (l == 0) { sh_s[w] = s; sh_ss[w] = ss; }
    __syncthreads();
    float stot = 0.f, sstot = 0.f;
    #pragma unroll
    for (int i = 0; i < 8; i++) { stot += sh_s[i]; sstot += sh_ss[i]; }

    const float inv_n = 1.0f / (float)CDIM;
    const float mean = stot * inv_n;
    const float var  = sstot * inv_n - mean * mean;
    const float rstd = rsqrtf(var + 1e-5f);

    float o0 = (v0 - mean) * rstd * g[t]       + b[t];
    float o1 = (v1 - mean) * rstd * g[t + 256] + b[t + 256];
    float o2 = (t < 64) ? ((v2 - mean) * rstd * g[t + 512] + b[t + 512]) : 0.f;

    if (out_f) {
        out_f[row * (long)CDIM + t]       = o0;
        out_f[row * (long)CDIM + t + 256] = o1;
        if (t < 64) out_f[row * (long)CDIM + t + 512] = o2;
    }
    if (out_r) {
        out_r[row * (long)CDIM + t]       = tf32r(o0);
        out_r[row * (long)CDIM + t + 256] = tf32r(o1);
        if (t < 64) out_r[row * (long)CDIM + t + 512] = tf32r(o2);
    }
}

__global__ void round_kernel(const float* __restrict__ in, float* __restrict__ out, int n) {
    int i = blockIdx.x * blockDim.x + threadIdx.x;
    if (i < n) out[i] = tf32r(in[i]);
}

// ===========================================================================
extern "C" void kernel_launch(void* const* d_in, const int* in_sizes, int n_in,
                              void* d_out, int out_size)
{
    const float* x  = (const float*)d_in[0];
    const float* y  = (const float*)d_in[1];
    const float* Wq = (const float*)d_in[2];
    const float* Wk = (const float*)d_in[3];
    const float* Wv = (const float*)d_in[4];
    const float* Wp = (const float*)d_in[5];
    const float* bp = (const float*)d_in[6];
    const float* gx = (const float*)d_in[7];
    const float* bx = (const float*)d_in[8];
    const float* gy = (const float*)d_in[9];
    const float* by = (const float*)d_in[10];
    const float* gz = (const float*)d_in[11];
    const float* bz = (const float*)d_in[12];
    float* out = (float*)d_out;

    float *xnf, *xnr, *ynr, *wq, *wk, *wv, *wp, *q, *k, *vt, *o, *attn, *p;
    cudaGetSymbolAddress((void**)&xnf, g_xnf);
    cudaGetSymbolAddress((void**)&xnr, g_xnr);
    cudaGetSymbolAddress((void**)&ynr, g_ynr);
    cudaGetSymbolAddress((void**)&wq,  g_wq);
    cudaGetSymbolAddress((void**)&wk,  g_wk);
    cudaGetSymbolAddress((void**)&wv,  g_wv);
    cudaGetSymbolAddress((void**)&wp,  g_wp);
    cudaGetSymbolAddress((void**)&q,   g_q);
    cudaGetSymbolAddress((void**)&k,   g_k);
    cudaGetSymbolAddress((void**)&vt,  g_vt);
    cudaGetSymbolAddress((void**)&o,   g_o);
    cudaGetSymbolAddress((void**)&attn,g_attn);
    cudaGetSymbolAddress((void**)&p,   g_p);

    cudaFuncSetAttribute(mma_gemm<1>, cudaFuncAttributeMaxDynamicSharedMemorySize, SMEM_SZ);
    cudaFuncSetAttribute(mma_gemm<2>, cudaFuncAttributeMaxDynamicSharedMemorySize, SMEM_SZ);
    cudaFuncSetAttribute(mma_gemm<3>, cudaFuncAttributeMaxDynamicSharedMemorySize, SMEM_SZ);
    cudaFuncSetAttribute(mma_gemm<4>, cudaFuncAttributeMaxDynamicSharedMemorySize, SMEM_SZ);

    // 1. LayerNorms (+ tf32 rounding)
    ln_kernel<<<ROWS, 256>>>(x, gx, bx, xnf, xnr);
    ln_kernel<<<ROWS, 256>>>(y, gy, by, nullptr, ynr);

    // 2. round weights to tf32
    {
        const int n = CDIM * CDIM, nb = (n + 255) / 256;
        round_kernel<<<nb, 256>>>(Wq, wq, n);
        round_kernel<<<nb, 256>>>(Wk, wk, n);
        round_kernel<<<nb, 256>>>(Wv, wv, n);
        round_kernel<<<nb, 256>>>(Wp, wp, n);
    }

    // 3. projections: q = yn@Wq^T, k = xn@Wk^T, Vt = (xn@Wv^T)^T per batch
    {
        dim3 grid(5, 128, 1);
        mma_gemm<1><<<grid, 256, SMEM_SZ>>>(ynr, wq, q,  ROWS, CDIM, CDIM, 0, 0, 0, CDIM, nullptr, nullptr);
        mma_gemm<1><<<grid, 256, SMEM_SZ>>>(xnr, wk, k,  ROWS, CDIM, CDIM, 0, 0, 0, CDIM, nullptr, nullptr);
        mma_gemm<4><<<grid, 256, SMEM_SZ>>>(xnr, wv, vt, ROWS, CDIM, CDIM, 0, 0, 0, CDIM, nullptr, nullptr);
    }

    // 4. attn = sigmoid(q @ k^T / 24) per batch
    {
        dim3 grid(16, 16, BATCH);
        mma_gemm<2><<<grid, 256, SMEM_SZ>>>(q, k, attn, NTOK, NTOK, CDIM,
            (long)NTOK * CDIM, (long)NTOK * CDIM, (long)NTOK * NTOK, NTOK, nullptr, nullptr);
    }

    // 5. O = attn @ Vt^T per batch (M=2048, N=576, K=2048)
    {
        dim3 grid(5, 16, BATCH);
        mma_gemm<1><<<grid, 256, SMEM_SZ>>>(attn, vt, o, NTOK, CDIM, NTOK,
            (long)NTOK * NTOK, (long)CDIM * NTOK, (long)NTOK * CDIM, CDIM, nullptr, nullptr);
    }

    // 6. P = O @ Wp^T + bp + xn_full
    {
        dim3 grid(5, 128, 1);
        mma_gemm<3><<<grid, 256, SMEM_SZ>>>(o, wp, p, ROWS, CDIM, CDIM, 0, 0, 0, CDIM, bp, xnf);
    }

    // 7. out = LN(P)
    ln_kernel<<<ROWS, 256>>>(p, gz, bz, out, nullptr);
}

// round 6
// speedup vs baseline: 4.9855x; 1.8441x over previous
#include <cuda_runtime.h>
#include <cuda_fp16.h>
#include <cstdint>

// ===========================================================================
// Cross_26998164423018  (B=8, N=2048, C=576, H=1)
// Round 4: fp16 mma.sync m16n8k16 (same 10-bit mantissa as tf32, 2x rate),
// fp32 accumulate, 4-stage cp.async pipeline, BK=32.
// ===========================================================================

#define CDIM   576
#define NTOK   2048
#define BATCH  8
#define ROWS   (BATCH * NTOK)          // 16384
#define ATT_SCALE 0.0416666679f        // 1/24

#define STAGES      4
#define ROW_HALVES  40                 // 32 data + 8 pad (80B row)
#define TILE_BYTES  (128 * ROW_HALVES * 2)          // 10240
#define STAGE_BYTES (2 * TILE_BYTES)                // A+B = 20480
#define EH          136                // half epilogue stride
#define EF          132                // float epilogue stride
#define SMEM_SZ     (STAGES * STAGE_BYTES)          // 81920

// ------------------------- scratch (static device mem) ---------------------
__device__ float  g_xnf[(size_t)ROWS * CDIM];      // fp32 xn (residual)
__device__ __half g_xnh[(size_t)ROWS * CDIM];
__device__ __half g_ynh[(size_t)ROWS * CDIM];
__device__ __half g_wq [(size_t)CDIM * CDIM];
__device__ __half g_wk [(size_t)CDIM * CDIM];
__device__ __half g_wv [(size_t)CDIM * CDIM];
__device__ __half g_wp [(size_t)CDIM * CDIM];
__device__ __half g_q  [(size_t)ROWS * CDIM];
__device__ __half g_k  [(size_t)ROWS * CDIM];
__device__ __half g_vt [(size_t)BATCH * CDIM * NTOK];   // [b][n][t]
__device__ __half g_o  [(size_t)ROWS * CDIM];
__device__ __half g_attn[(size_t)BATCH * NTOK * NTOK];  // 67 MB
__device__ float  g_p  [(size_t)ROWS * CDIM];

// ------------------------------- helpers -----------------------------------
__device__ __forceinline__ uint32_t smem_u32(const void* p) {
    uint32_t a;
    asm("{ .reg .u64 t; cvta.to.shared.u64 t, %1; cvt.u32.u64 %0, t; }"
        : "=r"(a) : "l"(p));
    return a;
}
__device__ __forceinline__ void cpa16(uint32_t dst, const void* src, uint32_t sz) {
    asm volatile("cp.async.cg.shared.global [%0], [%1], 16, %2;"
                 :: "r"(dst), "l"(src), "r"(sz) : "memory");
}
__device__ __forceinline__ void cpa_commit() {
    asm volatile("cp.async.commit_group;" ::: "memory");
}
template<int Np> __device__ __forceinline__ void cpa_wait() {
    asm volatile("cp.async.wait_group %0;" :: "n"(Np) : "memory");
}
__device__ __forceinline__ void mma_f16(float* c, const uint32_t* a, const uint32_t* b) {
    asm volatile(
        "mma.sync.aligned.m16n8k16.row.col.f32.f16.f16.f32 "
        "{%0,%1,%2,%3}, {%4,%5,%6,%7}, {%8,%9}, {%0,%1,%2,%3};"
        : "+f"(c[0]), "+f"(c[1]), "+f"(c[2]), "+f"(c[3])
        : "r"(a[0]), "r"(a[1]), "r"(a[2]), "r"(a[3]), "r"(b[0]), "r"(b[1]));
}

// ===========================================================================
// fp16 mma.sync GEMM: C[M,N] = A[M,K] @ B[N,K]^T  (both K-major, half)
// grid: (x = N-tiles, y = M-tiles, z = batch), block = 256 (8 warps, 2x4)
// EPI: 1 = half store, 2 = sigmoid(x/24) half store,
//      3 = fp32 store + bias[n] + resid[m,n], 4 = transposed half store (Vt)
// ===========================================================================
template<int EPI>
__global__ __launch_bounds__(256) void mma_gemm(
    const __half* __restrict__ A, const __half* __restrict__ B,
    void* __restrict__ Cv, int M, int N, int K,
    long sAz, long sBz, long sCz, int ldC,
    const float* __restrict__ bias, const float* __restrict__ resid)
{
    extern __shared__ char smem[];
    const uint32_t sb = smem_u32(smem);
    const int tid  = threadIdx.x;
    const int lane = tid & 31;
    const int wid  = tid >> 5;
    const int m0 = blockIdx.y * 128;
    const int n0 = blockIdx.x * 128;
    const int z  = blockIdx.z;
    const int KT = K >> 5;

    // ---- gmem load mapping: thread owns row tid>>1, 32B half (tid&1) ----
    const int lrow  = tid >> 1;
    const int lhalf = tid & 1;
    const __half* aPtr = A + (size_t)z * sAz + (size_t)(m0 + lrow) * K + lhalf * 16;
    const int gn = n0 + lrow;
    const uint32_t bsz = (gn < N) ? 16u : 0u;
    const __half* bPtr = B + (size_t)z * sBz + (size_t)(gn < N ? gn : 0) * K + lhalf * 16;
    const uint32_t dA = sb + (uint32_t)lrow * (ROW_HALVES * 2) + (uint32_t)lhalf * 32;
    const uint32_t dB = dA + TILE_BYTES;

    auto load_stage = [&](int s, int kt) {
        const uint32_t so = (uint32_t)s * STAGE_BYTES;
        const int k0 = kt * 32;
        cpa16(dA + so,      aPtr + k0,     16u);
        cpa16(dA + so + 16, aPtr + k0 + 8, 16u);
        cpa16(dB + so,      bPtr + k0,     bsz);
        cpa16(dB + so + 16, bPtr + k0 + 8, bsz);
    };

    // ---- accumulators & frag coords ----
    float acc[4][4][4];
    #pragma unroll
    for (int mt = 0; mt < 4; mt++)
        #pragma unroll
        for (int nt = 0; nt < 4; nt++)
            #pragma unroll
            for (int i = 0; i < 4; i++) acc[mt][nt][i] = 0.f;

    const int warp_m = wid & 1;
    const int warp_n = wid >> 1;
    const int gid = lane >> 2;           // groupID 0..7
    const int tig = lane & 3;            // thread-in-group
    const int arow = warp_m * 64 + gid;
    const int brow = warp_n * 32 + gid;

    // ---- pipeline prologue: stages 0..2 ----
    load_stage(0, 0); cpa_commit();
    load_stage(1, 1); cpa_commit();
    load_stage(2, 2); cpa_commit();

    for (int kt = 0; kt < KT; kt++) {
        cpa_wait<2>();
        __syncthreads();
        if (kt + 3 < KT) load_stage((kt + 3) & (STAGES - 1), kt + 3);
        cpa_commit();

        const uint32_t* uAs = (const uint32_t*)(smem + (kt & (STAGES - 1)) * STAGE_BYTES);
        const uint32_t* uBs = uAs + 128 * (ROW_HALVES / 2);

        #pragma unroll
        for (int kk = 0; kk < 2; kk++) {
            const int kc = kk * 8 + tig;         // uint32 col index
            uint32_t af[4][4];
            #pragma unroll
            for (int mt = 0; mt < 4; mt++) {
                const int r = arow + mt * 16;
                af[mt][0] = uAs[r * 20 + kc];
                af[mt][1] = uAs[(r + 8) * 20 + kc];
                af[mt][2] = uAs[r * 20 + kc + 4];
                af[mt][3] = uAs[(r + 8) * 20 + kc + 4];
            }
            uint32_t bf[4][2];
            #pragma unroll
            for (int nt = 0; nt < 4; nt++) {
                const int n = brow + nt * 8;
                bf[nt][0] = uBs[n * 20 + kc];
                bf[nt][1] = uBs[n * 20 + kc + 4];
            }
            #pragma unroll
            for (int mt = 0; mt < 4; mt++)
                #pragma unroll
                for (int nt = 0; nt < 4; nt++)
                    mma_f16(acc[mt][nt], af[mt], bf[nt]);
        }
    }

    // drain pending prefetches before reusing smem
    cpa_wait<0>();
    __syncthreads();

    // -------------------------------- epilogue --------------------------------
    if (EPI == 3) {
        float* eb = (float*)smem;   // [128][EF]
        #pragma unroll
        for (int mt = 0; mt < 4; mt++)
            #pragma unroll
            for (int i = 0; i < 4; i++) {
                const int r = warp_m * 64 + mt * 16 + gid + ((i >= 2) ? 8 : 0);
                #pragma unroll
                for (int nt = 0; nt < 4; nt++) {
                    const int c = warp_n * 32 + nt * 8 + tig * 2 + (i & 1);
                    eb[r * EF + c] = acc[mt][nt][i];
                }
            }
        __syncthreads();
        float* C = (float*)Cv;
        #pragma unroll
        for (int it = 0; it < 16; it++) {
            const int lin = it * 256 + tid;
            const int c4 = lin & 31, r = lin >> 5;
            const int n = n0 + c4 * 4;
            if (n < N) {
                float4 v4 = *(const float4*)(eb + r * EF + c4 * 4);
                const float4 bb = *(const float4*)(bias + n);
                const float4 rr = *(const float4*)(resid + (size_t)(m0 + r) * ldC + n);
                v4.x += bb.x + rr.x; v4.y += bb.y + rr.y;
                v4.z += bb.z + rr.z; v4.w += bb.w + rr.w;
                *(float4*)(C + (size_t)(m0 + r) * ldC + n) = v4;
            }
        }
        return;
    }

    __half* ebh = (__half*)smem;
    if (EPI == 4) {
        // transposed staging: ebh[n_local][t_local]
        #pragma unroll
        for (int mt = 0; mt < 4; mt++)
            #pragma unroll
            for (int i = 0; i < 4; i++) {
                const int r = warp_m * 64 + mt * 16 + gid + ((i >= 2) ? 8 : 0);
                #pragma unroll
                for (int nt = 0; nt < 4; nt++) {
                    const int c = warp_n * 32 + nt * 8 + tig * 2 + (i & 1);
                    ebh[c * EH + r] = __float2half_rn(acc[mt][nt][i]);
                }
            }
        __syncthreads();
        const int b = m0 >> 11, t0 = m0 & 2047;
        __half* vb = (__half*)Cv + (size_t)b * CDIM * NTOK + t0;
        #pragma unroll
        for (int it = 0; it < 8; it++) {
            const int lin = it * 256 + tid;
            const int t8 = (lin & 15) * 8, n = lin >> 4;
            if (n0 + n < N)
                *(uint4*)(vb + (size_t)(n0 + n) * NTOK + t8) =
                    *(const uint4*)(ebh + n * EH + t8);
        }
        return;
    }

    // EPI 1 / 2: half store, optionally sigmoid
    #pragma unroll
    for (int mt = 0; mt < 4; mt++)
        #pragma unroll
        for (int ih = 0; ih < 2; ih++) {       // c0c1 then c2c3 (row +8)
            const int r = warp_m * 64 + mt * 16 + gid + ih * 8;
            #pragma unroll
            for (int nt = 0; nt < 4; nt++) {
                const int c = warp_n * 32 + nt * 8 + tig * 2;
                float v0 = acc[mt][nt][ih * 2], v1 = acc[mt][nt][ih * 2 + 1];
                if (EPI == 2) {
                    v0 = 1.0f / (1.0f + __expf(-v0 * ATT_SCALE));
                    v1 = 1.0f / (1.0f + __expf(-v1 * ATT_SCALE));
                }
                *(__half2*)(ebh + r * EH + c) = __floats2half2_rn(v0, v1);
            }
        }
    __syncthreads();
    {
        __half* C = (__half*)Cv + (size_t)z * sCz;
        #pragma unroll
        for (int it = 0; it < 8; it++) {
            const int lin = it * 256 + tid;
            const int c8 = lin & 15, r = lin >> 4;
            const int n = n0 + c8 * 8;
            if (n < N)
                *(uint4*)(C + (size_t)(m0 + r) * ldC + n) =
                    *(const uint4*)(ebh + r * EH + c8 * 8);
        }
    }
}

// ===========================================================================
// LayerNorm over 576; writes fp32 and/or half output.
// ===========================================================================
__global__ __launch_bounds__(256) void ln_kernel(
    const float* __restrict__ x, const float* __restrict__ g,
    const float* __restrict__ b, float* __restrict__ out_f,
    __half* __restrict__ out_h)
{
    const long row = blockIdx.x;
    const float* xr = x + row * (long)CDIM;
    const int t = threadIdx.x;

    float v0 = xr[t];
    float v1 = xr[t + 256];
    float v2 = (t < 64) ? xr[t + 512] : 0.f;

    float s  = v0 + v1 + v2;
    float ss = v0 * v0 + v1 * v1 + v2 * v2;
    #pragma unroll
    for (int o = 16; o > 0; o >>= 1) {
        s  += __shfl_xor_sync(0xFFFFFFFFu, s,  o);
        ss += __shfl_xor_sync(0xFFFFFFFFu, ss, o);
    }
    __shared__ float sh_s[8], sh_ss[8];
    const int w = t >> 5, l = t & 31;
    if (l == 0) { sh_s[w] = s; sh_ss[w] = ss; }
    __syncthreads();
    float stot = 0.f, sstot = 0.f;
    #pragma unroll
    for (int i = 0; i < 8; i++) { stot += sh_s[i]; sstot += sh_ss[i]; }

    const float inv_n = 1.0f / (float)CDIM;
    const float mean = stot * inv_n;
    const float var  = sstot * inv_n - mean * mean;
    const float rstd = rsqrtf(var + 1e-5f);

    float o0 = (v0 - mean) * rstd * g[t]       + b[t];
    float o1 = (v1 - mean) * rstd * g[t + 256] + b[t + 256];
    float o2 = (t < 64) ? ((v2 - mean) * rstd * g[t + 512] + b[t + 512]) : 0.f;

    if (out_f) {
        out_f[row * (long)CDIM + t]       = o0;
        out_f[row * (long)CDIM + t + 256] = o1;
        if (t < 64) out_f[row * (long)CDIM + t + 512] = o2;
    }
    if (out_h) {
        out_h[row * (long)CDIM + t]       = __float2half_rn(o0);
        out_h[row * (long)CDIM + t + 256] = __float2half_rn(o1);
        if (t < 64) out_h[row * (long)CDIM + t + 512] = __float2half_rn(o2);
    }
}

__global__ void h_convert(const float* __restrict__ in, __half* __restrict__ out, int n) {
    int i = blockIdx.x * blockDim.x + threadIdx.x;
    if (i < n) out[i] = __float2half_rn(in[i]);
}

// ===========================================================================
extern "C" void kernel_launch(void* const* d_in, const int* in_sizes, int n_in,
                              void* d_out, int out_size)
{
    const float* x  = (const float*)d_in[0];
    const float* y  = (const float*)d_in[1];
    const float* Wq = (const float*)d_in[2];
    const float* Wk = (const float*)d_in[3];
    const float* Wv = (const float*)d_in[4];
    const float* Wp = (const float*)d_in[5];
    const float* bp = (const float*)d_in[6];
    const float* gx = (const float*)d_in[7];
    const float* bx = (const float*)d_in[8];
    const float* gy = (const float*)d_in[9];
    const float* by = (const float*)d_in[10];
    const float* gz = (const float*)d_in[11];
    const float* bz = (const float*)d_in[12];
    float* out = (float*)d_out;

    float *xnf, *p;
    __half *xnh, *ynh, *wq, *wk, *wv, *wp, *q, *k, *vt, *o, *attn;
    cudaGetSymbolAddress((void**)&xnf, g_xnf);
    cudaGetSymbolAddress((void**)&xnh, g_xnh);
    cudaGetSymbolAddress((void**)&ynh, g_ynh);
    cudaGetSymbolAddress((void**)&wq,  g_wq);
    cudaGetSymbolAddress((void**)&wk,  g_wk);
    cudaGetSymbolAddress((void**)&wv,  g_wv);
    cudaGetSymbolAddress((void**)&wp,  g_wp);
    cudaGetSymbolAddress((void**)&q,   g_q);
    cudaGetSymbolAddress((void**)&k,   g_k);
    cudaGetSymbolAddress((void**)&vt,  g_vt);
    cudaGetSymbolAddress((void**)&o,   g_o);
    cudaGetSymbolAddress((void**)&attn,g_attn);
    cudaGetSymbolAddress((void**)&p,   g_p);

    cudaFuncSetAttribute(mma_gemm<1>, cudaFuncAttributeMaxDynamicSharedMemorySize, SMEM_SZ);
    cudaFuncSetAttribute(mma_gemm<2>, cudaFuncAttributeMaxDynamicSharedMemorySize, SMEM_SZ);
    cudaFuncSetAttribute(mma_gemm<3>, cudaFuncAttributeMaxDynamicSharedMemorySize, SMEM_SZ);
    cudaFuncSetAttribute(mma_gemm<4>, cudaFuncAttributeMaxDynamicSharedMemorySize, SMEM_SZ);

    // 1. LayerNorms (fp32 residual copy + half operand copy)
    ln_kernel<<<ROWS, 256>>>(x, gx, bx, xnf, xnh);
    ln_kernel<<<ROWS, 256>>>(y, gy, by, nullptr, ynh);

    // 2. weights -> half
    {
        const int n = CDIM * CDIM, nb = (n + 255) / 256;
        h_convert<<<nb, 256>>>(Wq, wq, n);
        h_convert<<<nb, 256>>>(Wk, wk, n);
        h_convert<<<nb, 256>>>(Wv, wv, n);
        h_convert<<<nb, 256>>>(Wp, wp, n);
    }

    // 3. projections: q = yn@Wq^T, k = xn@Wk^T, Vt = (xn@Wv^T)^T per batch
    {
        dim3 grid(5, 128, 1);
        mma_gemm<1><<<grid, 256, SMEM_SZ>>>(ynh, wq, q,  ROWS, CDIM, CDIM, 0, 0, 0, CDIM, nullptr, nullptr);
        mma_gemm<1><<<grid, 256, SMEM_SZ>>>(xnh, wk, k,  ROWS, CDIM, CDIM, 0, 0, 0, CDIM, nullptr, nullptr);
        mma_gemm<4><<<grid, 256, SMEM_SZ>>>(xnh, wv, vt, ROWS, CDIM, CDIM, 0, 0, 0, CDIM, nullptr, nullptr);
    }

    // 4. attn = sigmoid(q @ k^T / 24) per batch, half
    {
        dim3 grid(16, 16, BATCH);
        mma_gemm<2><<<grid, 256, SMEM_SZ>>>(q, k, attn, NTOK, NTOK, CDIM,
            (long)NTOK * CDIM, (long)NTOK * CDIM, (long)NTOK * NTOK, NTOK, nullptr, nullptr);
    }

    // 5. O = attn @ Vt^T per batch (M=2048, N=576, K=2048)
    {
        dim3 grid(5, 16, BATCH);
        mma_gemm<1><<<grid, 256, SMEM_SZ>>>(attn, vt, o, NTOK, CDIM, NTOK,
            (long)NTOK * NTOK, (long)CDIM * NTOK, (long)NTOK * CDIM, CDIM, nullptr, nullptr);
    }

    // 6. P = O @ Wp^T + bp + xn_full  (fp32 out)
    {
        dim3 grid(5, 128, 1);
        mma_gemm<3><<<grid, 256, SMEM_SZ>>>(o, wp, p, ROWS, CDIM, CDIM, 0, 0, 0, CDIM, bp, xnf);
    }

    // 7. out = LN(P)
    ln_kernel<<<ROWS, 256>>>(p, gz, bz, out, nullptr);
}